// round 6
// baseline (speedup 1.0000x reference)
#include <cuda_runtime.h>

// ShiftedConv2d_25872882991120 — R6
//
// Analytic collapse (bit-exact since R1): output is all zeros except
//   out[b, c*16+s, 0, 0] = tens[b,c,127,127] * filters[s,0,0,0]
// for each s with shifts[s] == (7,7).
//
// R5 post-mortem: five write-path variants all pin at 37.3-38.6 us; DRAM
// busy only ~71% while payload is 7.2 TB/s -> hypothesis: limiter is the
// LTS handling every line twice (write-allocate + dirty writeback).
// R6 test: write-through stores (__stwt / STG.WT) skip the dirty-line
// pass. If flat/worse, R4 is the confirmed roofline answer.

#define PLANES     4096                    // B*C*S = 8*32*16
#define PLANE_V4   4096                    // 128*128 floats / 4
#define OUT_V4     (PLANES * PLANE_V4)     // 16,777,216 float4 (256 MiB)
#define THREADS    256
#define V4_PER_THR 4                       // chunk = 1024 float4 per block

__global__ void __launch_bounds__(THREADS)
shifted_conv_fill_wt_kernel(const float* __restrict__ tens,
                            const float* __restrict__ filters,
                            const int*   __restrict__ shifts,
                            float4* __restrict__ out)
{
    const unsigned base = blockIdx.x * (THREADS * V4_PER_THR) + threadIdx.x;

    const float4 z = make_float4(0.f, 0.f, 0.f, 0.f);
    float4 v0 = z;

    // Plane heads are at v4 offsets k*4096; chunk size 1024 divides 4096,
    // so a head is always a chunk's first element: tid==0 && blockIdx%4==0.
    if (threadIdx.x == 0 && (blockIdx.x & 3u) == 0u) {
        const unsigned plane = blockIdx.x >> 2;
        const unsigned s = plane & 15u;
        const int sh0 = shifts[2u * s];
        const int sh1 = shifts[2u * s + 1u];
        if (sh0 == 7 && sh1 == 7) {
            const unsigned c = (plane >> 4) & 31u;
            const unsigned b = plane >> 9;
            const unsigned n = b * 32u + c;
            v0.x = tens[(n * 128u + 127u) * 128u + 127u] * filters[s * 49u];
        }
    }

    // 4 independent write-through STG.128 per thread; each warp iteration
    // is a contiguous 2 KB burst. No L2 dirty-line allocation/writeback.
    __stwt(out + base,               v0);
    __stwt(out + base + 1 * THREADS, z);
    __stwt(out + base + 2 * THREADS, z);
    __stwt(out + base + 3 * THREADS, z);
}

extern "C" void kernel_launch(void* const* d_in, const int* in_sizes, int n_in,
                              void* d_out, int out_size)
{
    const float* tens    = (const float*)d_in[0];
    const float* filters = (const float*)d_in[1];
    const int*   shifts  = (const int*)d_in[2];
    float4*      out     = (float4*)d_out;

    (void)in_sizes; (void)n_in; (void)out_size;

    // 16,777,216 v4 / (256 thr * 4 v4) = 16384 blocks, exact cover.
    shifted_conv_fill_wt_kernel<<<OUT_V4 / (THREADS * V4_PER_THR), THREADS>>>(
        tens, filters, shifts, out);
}

// round 7
// speedup vs baseline: 1.0331x; 1.0331x over previous
#include <cuda_runtime.h>

// ShiftedConv2d_25872882991120 — FINAL (R4 configuration, held)
//
// Analytic collapse (bit-exact vs reference, rel_err = 0.0 every round):
//   _roll_mask keeps only the wrap-around region (i < s); with the right/
//   bottom zero-padding, the rolled tensor is nonzero solely when
//   shifts[s] == (7,7), at position (0,0), value tens[b,c,127,127].
//   VALID 7x7 cross-correlation of that single point gives
//     out[b, c*16+s, 0, 0] = tens[b,c,127,127] * filters[s,0,0,0]
//   and exact zeros everywhere else.
//
// Roofline verdict (R1-R6): six write paths (plain STG, deep-batch STG,
// memset engine, STG.CS x4/x8, STG.WT) all pin at 37.3-37.6 us kernel
// time for the 256 MiB output stream -> DRAM-write roofline, payload
// ~7.2 TB/s. This R4 config was the fastest measured; held as final.

#define PLANES     4096                    // B*C*S = 8*32*16
#define PLANE_V4   4096                    // 128*128 floats / 4
#define OUT_V4     (PLANES * PLANE_V4)     // 16,777,216 float4 (256 MiB)
#define THREADS    256
#define V4_PER_THR 4

__global__ void __launch_bounds__(THREADS)
shifted_conv_fill_cs_kernel(const float* __restrict__ tens,
                            const float* __restrict__ filters,
                            const int*   __restrict__ shifts,
                            float4* __restrict__ out)
{
    // Each block owns a contiguous chunk of THREADS*V4_PER_THR = 1024 float4.
    const unsigned base = blockIdx.x * (THREADS * V4_PER_THR) + threadIdx.x;

    const float4 z = make_float4(0.f, 0.f, 0.f, 0.f);
    float4 v0 = z;

    // Plane heads sit at v4 indices that are multiples of PLANE_V4 (4096).
    // Chunk size 1024 divides 4096, so a head can only be the chunk's first
    // element: threadIdx.x == 0 and blockIdx.x % 4 == 0.
    if (threadIdx.x == 0 && (blockIdx.x & 3u) == 0u) {
        const unsigned plane = blockIdx.x >> 2;      // base / PLANE_V4
        const unsigned s = plane & 15u;
        const int sh0 = shifts[2u * s];
        const int sh1 = shifts[2u * s + 1u];
        if (sh0 == 7 && sh1 == 7) {
            const unsigned c = (plane >> 4) & 31u;
            const unsigned b = plane >> 9;
            const unsigned n = b * 32u + c;
            v0.x = tens[(n * 128u + 127u) * 128u + 127u] * filters[s * 49u];
        }
    }

    // 4 independent streaming STG.128 per thread; each warp iteration is a
    // contiguous 2 KB burst (full 128B lines).
    __stcs(out + base,               v0);
    __stcs(out + base + 1 * THREADS, z);
    __stcs(out + base + 2 * THREADS, z);
    __stcs(out + base + 3 * THREADS, z);
}

extern "C" void kernel_launch(void* const* d_in, const int* in_sizes, int n_in,
                              void* d_out, int out_size)
{
    const float* tens    = (const float*)d_in[0];
    const float* filters = (const float*)d_in[1];
    const int*   shifts  = (const int*)d_in[2];
    float4*      out     = (float4*)d_out;

    (void)in_sizes; (void)n_in; (void)out_size;

    // 16,777,216 v4 / (256 thr * 4 v4) = 16384 blocks, exact cover.
    shifted_conv_fill_cs_kernel<<<OUT_V4 / (THREADS * V4_PER_THR), THREADS>>>(
        tens, filters, shifts, out);
}

// round 8
// speedup vs baseline: 1.0415x; 1.0081x over previous
#include <cuda_runtime.h>

// ShiftedConv2d_25872882991120 — FINAL (R4 configuration, held; reproduced
// at 37.22us kernel / 39.68us bench in R7)
//
// Analytic collapse (bit-exact vs reference, rel_err = 0.0 every round):
//   _roll_mask keeps only the wrap-around region (i < s); with the right/
//   bottom zero-padding, the rolled tensor is nonzero solely when
//   shifts[s] == (7,7), at position (0,0), value tens[b,c,127,127].
//   VALID 7x7 cross-correlation of that single point gives
//     out[b, c*16+s, 0, 0] = tens[b,c,127,127] * filters[s,0,0,0]
//   and exact zeros everywhere else.
//
// Roofline verdict (R1-R7): six distinct write paths (plain STG, deep-batch
// STG, memset engine, STG.CS x4/x8, STG.WT) all pin at 37.2-37.6 us kernel
// time for the 256 MiB output stream -> pure-write DRAM roofline, payload
// ~7.2 TB/s (~90% of the 8 TB/s read+write aggregate spec). This config was
// the fastest measured and reproduces; held as final.

#define PLANES     4096                    // B*C*S = 8*32*16
#define PLANE_V4   4096                    // 128*128 floats / 4
#define OUT_V4     (PLANES * PLANE_V4)     // 16,777,216 float4 (256 MiB)
#define THREADS    256
#define V4_PER_THR 4

__global__ void __launch_bounds__(THREADS)
shifted_conv_fill_cs_kernel(const float* __restrict__ tens,
                            const float* __restrict__ filters,
                            const int*   __restrict__ shifts,
                            float4* __restrict__ out)
{
    // Each block owns a contiguous chunk of THREADS*V4_PER_THR = 1024 float4.
    const unsigned base = blockIdx.x * (THREADS * V4_PER_THR) + threadIdx.x;

    const float4 z = make_float4(0.f, 0.f, 0.f, 0.f);
    float4 v0 = z;

    // Plane heads sit at v4 indices that are multiples of PLANE_V4 (4096).
    // Chunk size 1024 divides 4096, so a head can only be the chunk's first
    // element: threadIdx.x == 0 and blockIdx.x % 4 == 0.
    if (threadIdx.x == 0 && (blockIdx.x & 3u) == 0u) {
        const unsigned plane = blockIdx.x >> 2;      // base / PLANE_V4
        const unsigned s = plane & 15u;
        const int sh0 = shifts[2u * s];
        const int sh1 = shifts[2u * s + 1u];
        if (sh0 == 7 && sh1 == 7) {
            const unsigned c = (plane >> 4) & 31u;
            const unsigned b = plane >> 9;
            const unsigned n = b * 32u + c;
            v0.x = tens[(n * 128u + 127u) * 128u + 127u] * filters[s * 49u];
        }
    }

    // 4 independent streaming STG.128 per thread; each warp iteration is a
    // contiguous 2 KB burst (full 128B lines).
    __stcs(out + base,               v0);
    __stcs(out + base + 1 * THREADS, z);
    __stcs(out + base + 2 * THREADS, z);
    __stcs(out + base + 3 * THREADS, z);
}

extern "C" void kernel_launch(void* const* d_in, const int* in_sizes, int n_in,
                              void* d_out, int out_size)
{
    const float* tens    = (const float*)d_in[0];
    const float* filters = (const float*)d_in[1];
    const int*   shifts  = (const int*)d_in[2];
    float4*      out     = (float4*)d_out;

    (void)in_sizes; (void)n_in; (void)out_size;

    // 16,777,216 v4 / (256 thr * 4 v4) = 16384 blocks, exact cover.
    shifted_conv_fill_cs_kernel<<<OUT_V4 / (THREADS * V4_PER_THR), THREADS>>>(
        tens, filters, shifts, out);
}